// round 14
// baseline (speedup 1.0000x reference)
#include <cuda_runtime.h>
#include <cuda_fp16.h>
#include <cstdint>
#include <math.h>

#define GM 65536
#define GK 768
#define GN 768

// ---------------------------------------------------------------------------
// Device scratch (allocation-free rule: __device__ globals)
// ---------------------------------------------------------------------------
__device__ __half g_Qh[(size_t)GM * GN];
__device__ __half g_Kh[(size_t)GM * GN];
__device__ __half g_Vh[(size_t)GM * GN];
__device__ __half g_Xh[(size_t)GM * GK];
__device__ __half g_Wh[3][(size_t)GN * GK];

// ---------------------------------------------------------------------------
// Baseline-ISA helpers (compute_103-safe)
// ---------------------------------------------------------------------------
__device__ __forceinline__ uint32_t smem_u32(const void* p) {
    uint32_t a;
    asm("{ .reg .u64 t; cvta.to.shared.u64 t, %1; cvt.u32.u64 %0, t; }"
        : "=r"(a) : "l"(p));
    return a;
}

__device__ __forceinline__ void cp_async16(uint32_t saddr, const void* gptr) {
    asm volatile("cp.async.cg.shared.global [%0], [%1], 16;"
                 :: "r"(saddr), "l"(gptr) : "memory");
}
#define CP_COMMIT() asm volatile("cp.async.commit_group;" ::: "memory")
#define CP_WAIT1()  asm volatile("cp.async.wait_group 1;" ::: "memory")

__device__ __forceinline__ void ldsm_x4(uint32_t* r, uint32_t addr) {
    asm volatile("ldmatrix.sync.aligned.m8n8.x4.shared.b16 {%0,%1,%2,%3}, [%4];"
                 : "=r"(r[0]), "=r"(r[1]), "=r"(r[2]), "=r"(r[3]) : "r"(addr));
}
__device__ __forceinline__ void ldsm_x4_t(uint32_t* r, uint32_t addr) {
    asm volatile("ldmatrix.sync.aligned.m8n8.x4.trans.shared.b16 {%0,%1,%2,%3}, [%4];"
                 : "=r"(r[0]), "=r"(r[1]), "=r"(r[2]), "=r"(r[3]) : "r"(addr));
}
// fp16 HMMA, fp32 accumulate
__device__ __forceinline__ void mma16816(float* c, const uint32_t* a, const uint32_t* b) {
    asm volatile(
        "mma.sync.aligned.m16n8k16.row.col.f32.f16.f16.f32 "
        "{%0,%1,%2,%3}, {%4,%5,%6,%7}, {%8,%9}, {%0,%1,%2,%3};"
        : "+f"(c[0]), "+f"(c[1]), "+f"(c[2]), "+f"(c[3])
        : "r"(a[0]), "r"(a[1]), "r"(a[2]), "r"(a[3]), "r"(b[0]), "r"(b[1]));
}
__device__ __forceinline__ uint32_t pack_f16(float lo, float hi) {
    __half2 h = __floats2half2_rn(lo, hi);
    return *(uint32_t*)&h;
}

// ---------------------------------------------------------------------------
// fp32 -> fp16 convert
// ---------------------------------------------------------------------------
__global__ void to_f16(const float* __restrict__ src, __half* __restrict__ dst, int n4)
{
    int i = blockIdx.x * blockDim.x + threadIdx.x;
    if (i >= n4) return;
    float4 v = ((const float4*)src)[i];
    uint32_t* D = (uint32_t*)dst;
    D[2 * i]     = pack_f16(v.x, v.y);
    D[2 * i + 1] = pack_f16(v.z, v.w);
}

// ---------------------------------------------------------------------------
// fp16 HMMA QKV GEMM: C = A @ W^T + bias.
// CTA 128(M) x 256(N), BK=64, 8 warps (2m x 4n), warp tile 64x64.
// LDSM:MMA = 8:32 per k16-step; A L2 re-reads cut 18x -> 9x.
// smem rows padded to 72 fp16 (144 B) -> conflict-free ldmatrix.
// ---------------------------------------------------------------------------
#define BM 128
#define BN 256
#define BK 64
#define NCHUNK (GK / BK)                 // 12
#define ROWH 72
#define ROWB 144
#define A_TILE_B (128 * ROWB)            // 18432 B
#define B_TILE_B (256 * ROWB)            // 36864 B
#define STAGE_B (A_TILE_B + B_TILE_B)    // 55296 B
#define GEMM_SMEM (2 * STAGE_B)          // 110592 B

__device__ __forceinline__ void load_chunk(uint32_t st,
                                           const __half* A, const __half* B,
                                           int bm, int bn, int k0, int tid)
{
#pragma unroll
    for (int t = 0; t < 4; ++t) {        // A: 128 rows x 8 segs = 1024
        int id  = tid + t * 256;
        int r   = id >> 3;
        int seg = (id & 7) * 8;
        cp_async16(st + (uint32_t)(r * ROWB + seg * 2),
                   A + (size_t)(bm + r) * GK + k0 + seg);
    }
#pragma unroll
    for (int t = 0; t < 8; ++t) {        // B: 256 rows x 8 segs = 2048
        int id  = tid + t * 256;
        int r   = id >> 3;
        int seg = (id & 7) * 8;
        cp_async16(st + A_TILE_B + (uint32_t)(r * ROWB + seg * 2),
                   B + (size_t)(bn + r) * GK + k0 + seg);
    }
}

__global__ __launch_bounds__(256, 1)
void gemm_hmma(const float* __restrict__ bq, const float* __restrict__ bk,
               const float* __restrict__ bv)
{
    extern __shared__ __align__(128) char smem[];
    const int tid  = threadIdx.x;
    const int wid  = tid >> 5;
    const int lane = tid & 31;
    const int sel  = blockIdx.x / 3;     // 3 mats
    const int nt3  = blockIdx.x % 3;     // 3 N-tiles of 256
    const int bm   = blockIdx.y * BM;
    const int bn   = nt3 * BN;
    const int wm   = wid >> 2;           // 0-1 -> 64 M rows
    const int wn   = wid & 3;            // 0-3 -> 64 N cols

    const __half* __restrict__ A = g_Xh;
    const __half* __restrict__ B = g_Wh[sel];
    __half* __restrict__ C = (sel == 0) ? g_Qh : (sel == 1) ? g_Kh : g_Vh;
    const float* __restrict__ bias = (sel == 0) ? bq : (sel == 1) ? bk : bv;

    const uint32_t sb = smem_u32(smem);

    float acc[4][8][4];
#pragma unroll
    for (int i = 0; i < 4; i++)
#pragma unroll
        for (int j = 0; j < 8; j++)
#pragma unroll
            for (int u = 0; u < 4; u++) acc[i][j][u] = 0.f;

    load_chunk(sb, A, B, bm, bn, 0, tid);
    CP_COMMIT();
    load_chunk(sb + STAGE_B, A, B, bm, bn, BK, tid);
    CP_COMMIT();

    // A-frag: rows wm*64 + mt*16 + (lane&15), k-half (lane>>4)*8
    const uint32_t a_row  = (uint32_t)(wm * 64 + (lane & 15));
    const uint32_t a_koff = (uint32_t)((lane >> 4) << 3);
    // B-frag x4 (16 n per group): n = wn*64 + g*16 + (lane&7) + ((lane>>4)&1)*8
    const uint32_t b_row  = (uint32_t)(wn * 64 + (lane & 7) + (((lane >> 4) & 1) << 3));
    const uint32_t b_koff = (uint32_t)(((lane >> 3) & 1) << 3);

    for (int c = 0; c < NCHUNK; ++c) {
        CP_WAIT1();
        __syncthreads();
        const uint32_t st = sb + (uint32_t)(c & 1) * STAGE_B;

#pragma unroll
        for (int ks = 0; ks < 4; ++ks) {
            const uint32_t k0 = ks * 16;
            uint32_t af[4][4], bf[4][4];
#pragma unroll
            for (int mt = 0; mt < 4; ++mt) {
                uint32_t off = ((a_row + mt * 16) * ROWH + k0 + a_koff) * 2;
                ldsm_x4(af[mt], st + off);
            }
#pragma unroll
            for (int gb = 0; gb < 4; ++gb) {
                uint32_t off = ((b_row + gb * 16) * ROWH + k0 + b_koff) * 2;
                ldsm_x4(bf[gb], st + A_TILE_B + off);
            }
#pragma unroll
            for (int mt = 0; mt < 4; ++mt)
#pragma unroll
                for (int gb = 0; gb < 4; ++gb) {
                    mma16816(acc[mt][2 * gb],     af[mt], bf[gb]);
                    mma16816(acc[mt][2 * gb + 1], af[mt], bf[gb] + 2);
                }
        }

        __syncthreads();
        if (c + 2 < NCHUNK)
            load_chunk(sb + (uint32_t)(c & 1) * STAGE_B, A, B, bm, bn, (c + 2) * BK, tid);
        CP_COMMIT();
    }

    // Epilogue: bias add, fp16 store
#pragma unroll
    for (int nt = 0; nt < 8; ++nt) {
        const int col = bn + wn * 64 + nt * 8 + (lane & 3) * 2;
        const float2 bb = *(const float2*)(bias + col);
#pragma unroll
        for (int mt = 0; mt < 4; ++mt) {
            const int row = bm + wm * 64 + mt * 16 + (lane >> 2);
            size_t i0 = (size_t)row * GN + col;
            size_t i1 = (size_t)(row + 8) * GN + col;
            *(uint32_t*)(C + i0) = pack_f16(acc[mt][nt][0] + bb.x, acc[mt][nt][1] + bb.y);
            *(uint32_t*)(C + i1) = pack_f16(acc[mt][nt][2] + bb.x, acc[mt][nt][3] + bb.y);
        }
    }
}

// ---------------------------------------------------------------------------
// HMMA fused causal flash attention, plain fp16 Q/K/V (unchanged from R13).
// ---------------------------------------------------------------------------
#define FSTR 72
#define FTILE_B (64 * FSTR * 2)          // 9216 B per 64x64 fp16 tile
#define FQ_B FTILE_B
#define FSTAGE_B (2 * FTILE_B)           // Kh | Vh = 18432 B
#define FLASH_SMEM (FQ_B + 2 * FSTAGE_B) // 46080 B

__device__ __forceinline__ void flash_load_tile(uint32_t base, size_t krow0,
                                                int colh, int tid)
{
#pragma unroll
    for (int i = 0; i < 4; ++i) {
        int id  = tid + i * 128;
        int r   = id >> 3;
        int seg = (id & 7) * 16;
        uint32_t soff = (uint32_t)(r * 144 + seg);
        cp_async16(base + soff,           (const char*)(g_Kh + (krow0 + r) * GN + colh) + seg);
        cp_async16(base + FTILE_B + soff, (const char*)(g_Vh + (krow0 + r) * GN + colh) + seg);
    }
}

__global__ __launch_bounds__(128)
void flash_attn_tc(float* __restrict__ O)
{
    extern __shared__ __align__(128) char smem[];
    const int tid  = threadIdx.x;
    const int warp = tid >> 5;
    const int lane = tid & 31;
    const int qt   = blockIdx.x;
    const int h    = blockIdx.y;
    const int g    = blockIdx.z;
    const int colh = h * 64;
    const size_t qrow0 = (size_t)g * 256 + qt * 64;
    const uint32_t sb = smem_u32(smem);

#pragma unroll
    for (int i = 0; i < 4; ++i) {
        int id  = tid + i * 128;
        int r   = id >> 3;
        int seg = (id & 7) * 16;
        uint32_t soff = (uint32_t)(r * 144 + seg);
        cp_async16(sb + soff, (const char*)(g_Qh + (qrow0 + r) * GN + colh) + seg);
    }
    flash_load_tile(sb + FQ_B, (size_t)g * 256, colh, tid);
    CP_COMMIT();
    if (qt > 0) flash_load_tile(sb + FQ_B + FSTAGE_B, (size_t)g * 256 + 64, colh, tid);
    CP_COMMIT();

    const int lm = lane >> 3;
    const int lr = lane & 7;
    const int r0 = warp * 16;
    const uint32_t a_off0  = (uint32_t)(((r0 + (lm & 1) * 8 + lr) * FSTR + (lm >> 1) * 8) * 2);
    const uint32_t kb_off0 = (uint32_t)((((lm >> 1) * 8 + lr) * FSTR + (lm & 1) * 8) * 2);
    const uint32_t vb_off0 = (uint32_t)((((lm & 1) * 8 + lr) * FSTR + (lm >> 1) * 8) * 2);

    uint32_t qh[4][4];
    float m_[2] = {-1e30f, -1e30f};
    float l_[2] = {0.f, 0.f};
    float o[8][4];
#pragma unroll
    for (int j = 0; j < 8; ++j)
#pragma unroll
        for (int c = 0; c < 4; ++c) o[j][c] = 0.f;

    const int ra = warp * 16 + (lane >> 2);
    const int rb = ra + 8;

    for (int kt = 0; kt <= qt; ++kt) {
        CP_WAIT1();
        __syncthreads();
        const uint32_t kb = sb + FQ_B + (uint32_t)(kt & 1) * FSTAGE_B;

        if (kt == 0) {
#pragma unroll
            for (int kc = 0; kc < 4; ++kc)
                ldsm_x4(qh[kc], sb + a_off0 + kc * 32);
        }

        float s[8][4];
#pragma unroll
        for (int j = 0; j < 8; ++j)
#pragma unroll
            for (int c = 0; c < 4; ++c) s[j][c] = 0.f;

#pragma unroll
        for (int kc = 0; kc < 4; ++kc)
#pragma unroll
            for (int p = 0; p < 4; ++p) {
                uint32_t kh4[4];
                uint32_t off = kb_off0 + (uint32_t)((p * 16 * FSTR + kc * 16) * 2);
                ldsm_x4(kh4, kb + off);
                mma16816(s[2 * p],     qh[kc], kh4);
                mma16816(s[2 * p + 1], qh[kc], kh4 + 2);
            }

        const float scale = 0.125f;
#pragma unroll
        for (int j = 0; j < 8; ++j)
#pragma unroll
            for (int c = 0; c < 4; ++c) s[j][c] *= scale;
        if (kt == qt) {
#pragma unroll
            for (int j = 0; j < 8; ++j) {
                int k0j = j * 8 + (lane & 3) * 2;
                if (k0j     > ra) s[j][0] = -1e30f;
                if (k0j + 1 > ra) s[j][1] = -1e30f;
                if (k0j     > rb) s[j][2] = -1e30f;
                if (k0j + 1 > rb) s[j][3] = -1e30f;
            }
        }

        float mA = -1e30f, mB = -1e30f;
#pragma unroll
        for (int j = 0; j < 8; ++j) {
            mA = fmaxf(mA, fmaxf(s[j][0], s[j][1]));
            mB = fmaxf(mB, fmaxf(s[j][2], s[j][3]));
        }
        mA = fmaxf(mA, __shfl_xor_sync(0xffffffffu, mA, 1));
        mA = fmaxf(mA, __shfl_xor_sync(0xffffffffu, mA, 2));
        mB = fmaxf(mB, __shfl_xor_sync(0xffffffffu, mB, 1));
        mB = fmaxf(mB, __shfl_xor_sync(0xffffffffu, mB, 2));

        float mnA = fmaxf(m_[0], mA), mnB = fmaxf(m_[1], mB);
        float corrA = __expf(m_[0] - mnA), corrB = __expf(m_[1] - mnB);
        m_[0] = mnA; m_[1] = mnB;

        float rsA = 0.f, rsB = 0.f;
#pragma unroll
        for (int j = 0; j < 8; ++j) {
            s[j][0] = __expf(s[j][0] - mnA);
            s[j][1] = __expf(s[j][1] - mnA);
            s[j][2] = __expf(s[j][2] - mnB);
            s[j][3] = __expf(s[j][3] - mnB);
            rsA += s[j][0] + s[j][1];
            rsB += s[j][2] + s[j][3];
        }
        rsA += __shfl_xor_sync(0xffffffffu, rsA, 1);
        rsA += __shfl_xor_sync(0xffffffffu, rsA, 2);
        rsB += __shfl_xor_sync(0xffffffffu, rsB, 1);
        rsB += __shfl_xor_sync(0xffffffffu, rsB, 2);
        l_[0] = l_[0] * corrA + rsA;
        l_[1] = l_[1] * corrB + rsB;

#pragma unroll
        for (int j = 0; j < 8; ++j) {
            o[j][0] *= corrA; o[j][1] *= corrA;
            o[j][2] *= corrB; o[j][3] *= corrB;
        }

        uint32_t ph[4][4];
#pragma unroll
        for (int kc = 0; kc < 4; ++kc) {
            int j0 = 2 * kc, j1 = j0 + 1;
            ph[kc][0] = pack_f16(s[j0][0], s[j0][1]);
            ph[kc][1] = pack_f16(s[j0][2], s[j0][3]);
            ph[kc][2] = pack_f16(s[j1][0], s[j1][1]);
            ph[kc][3] = pack_f16(s[j1][2], s[j1][3]);
        }

#pragma unroll
        for (int kc = 0; kc < 4; ++kc)
#pragma unroll
            for (int p = 0; p < 4; ++p) {
                uint32_t vh4[4];
                uint32_t off = vb_off0 + (uint32_t)((kc * 16 * FSTR + p * 16) * 2);
                ldsm_x4_t(vh4, kb + FTILE_B + off);
                mma16816(o[2 * p],     ph[kc], vh4);
                mma16816(o[2 * p + 1], ph[kc], vh4 + 2);
            }

        __syncthreads();
        if (kt + 2 <= qt)
            flash_load_tile(sb + FQ_B + (uint32_t)(kt & 1) * FSTAGE_B,
                            (size_t)g * 256 + (kt + 2) * 64, colh, tid);
        CP_COMMIT();
    }

    const float invA = 1.0f / l_[0];
    const float invB = 1.0f / l_[1];
#pragma unroll
    for (int j = 0; j < 8; ++j) {
        const int col = colh + j * 8 + (lane & 3) * 2;
        const size_t rA = qrow0 + warp * 16 + (lane >> 2);
        float2 oa, ob;
        oa.x = o[j][0] * invA; oa.y = o[j][1] * invA;
        ob.x = o[j][2] * invB; ob.y = o[j][3] * invB;
        *(float2*)(O + rA * GN + col) = oa;
        *(float2*)(O + (rA + 8) * GN + col) = ob;
    }
}

// ---------------------------------------------------------------------------
extern "C" void kernel_launch(void* const* d_in, const int* in_sizes, int n_in,
                              void* d_out, int out_size)
{
    const float* X  = (const float*)d_in[0];
    const float* Wq = (const float*)d_in[1];
    const float* bq = (const float*)d_in[2];
    const float* Wk = (const float*)d_in[3];
    const float* bk = (const float*)d_in[4];
    const float* Wv = (const float*)d_in[5];
    const float* bv = (const float*)d_in[6];
    float* O = (float*)d_out;

    __half *xh, *wh;
    cudaGetSymbolAddress((void**)&xh, g_Xh);
    cudaGetSymbolAddress((void**)&wh, g_Wh);

    {
        int n4 = (GM * GK) / 4;
        to_f16<<<(n4 + 255) / 256, 256>>>(X, xh, n4);
        int w4 = (GN * GK) / 4;
        to_f16<<<(w4 + 255) / 256, 256>>>(Wq, wh + 0 * (size_t)GN * GK, w4);
        to_f16<<<(w4 + 255) / 256, 256>>>(Wk, wh + 1 * (size_t)GN * GK, w4);
        to_f16<<<(w4 + 255) / 256, 256>>>(Wv, wh + 2 * (size_t)GN * GK, w4);
    }

    cudaFuncSetAttribute(gemm_hmma, cudaFuncAttributeMaxDynamicSharedMemorySize, GEMM_SMEM);
    dim3 ggrid(9, GM / BM);
    gemm_hmma<<<ggrid, 256, GEMM_SMEM>>>(bq, bk, bv);

    cudaFuncSetAttribute(flash_attn_tc, cudaFuncAttributeMaxDynamicSharedMemorySize, FLASH_SMEM);
    dim3 agrid(4, 12, 256);
    flash_attn_tc<<<agrid, 128, FLASH_SMEM>>>(O);
}

// round 15
// speedup vs baseline: 1.2457x; 1.2457x over previous
#include <cuda_runtime.h>
#include <cuda_fp16.h>
#include <cstdint>
#include <math.h>

#define GM 65536
#define GK 768
#define GN 768

// ---------------------------------------------------------------------------
// Device scratch (allocation-free rule: __device__ globals)
// Q is pre-scaled by 0.125*log2(e) so flash softmax runs in exp2 domain.
// ---------------------------------------------------------------------------
__device__ __half g_Qh[(size_t)GM * GN];
__device__ __half g_Kh[(size_t)GM * GN];
__device__ __half g_Vh[(size_t)GM * GN];
__device__ __half g_Xh[(size_t)GM * GK];
__device__ __half g_Wh[3][(size_t)GN * GK];

// ---------------------------------------------------------------------------
// Baseline-ISA helpers (compute_103-safe)
// ---------------------------------------------------------------------------
__device__ __forceinline__ uint32_t smem_u32(const void* p) {
    uint32_t a;
    asm("{ .reg .u64 t; cvta.to.shared.u64 t, %1; cvt.u32.u64 %0, t; }"
        : "=r"(a) : "l"(p));
    return a;
}

__device__ __forceinline__ void cp_async16(uint32_t saddr, const void* gptr) {
    asm volatile("cp.async.cg.shared.global [%0], [%1], 16;"
                 :: "r"(saddr), "l"(gptr) : "memory");
}
#define CP_COMMIT() asm volatile("cp.async.commit_group;" ::: "memory")
#define CP_WAIT1()  asm volatile("cp.async.wait_group 1;" ::: "memory")
#define CP_WAIT2()  asm volatile("cp.async.wait_group 2;" ::: "memory")

__device__ __forceinline__ void ldsm_x4(uint32_t* r, uint32_t addr) {
    asm volatile("ldmatrix.sync.aligned.m8n8.x4.shared.b16 {%0,%1,%2,%3}, [%4];"
                 : "=r"(r[0]), "=r"(r[1]), "=r"(r[2]), "=r"(r[3]) : "r"(addr));
}
__device__ __forceinline__ void ldsm_x4_t(uint32_t* r, uint32_t addr) {
    asm volatile("ldmatrix.sync.aligned.m8n8.x4.trans.shared.b16 {%0,%1,%2,%3}, [%4];"
                 : "=r"(r[0]), "=r"(r[1]), "=r"(r[2]), "=r"(r[3]) : "r"(addr));
}
// fp16 HMMA, fp32 accumulate
__device__ __forceinline__ void mma16816(float* c, const uint32_t* a, const uint32_t* b) {
    asm volatile(
        "mma.sync.aligned.m16n8k16.row.col.f32.f16.f16.f32 "
        "{%0,%1,%2,%3}, {%4,%5,%6,%7}, {%8,%9}, {%0,%1,%2,%3};"
        : "+f"(c[0]), "+f"(c[1]), "+f"(c[2]), "+f"(c[3])
        : "r"(a[0]), "r"(a[1]), "r"(a[2]), "r"(a[3]), "r"(b[0]), "r"(b[1]));
}
__device__ __forceinline__ uint32_t pack_f16(float lo, float hi) {
    __half2 h = __floats2half2_rn(lo, hi);
    return *(uint32_t*)&h;
}
__device__ __forceinline__ float ex2(float x) {
    float y;
    asm("ex2.approx.ftz.f32 %0, %1;" : "=f"(y) : "f"(x));
    return y;
}

// ---------------------------------------------------------------------------
// fp32 -> fp16 convert
// ---------------------------------------------------------------------------
__global__ void to_f16(const float* __restrict__ src, __half* __restrict__ dst, int n4)
{
    int i = blockIdx.x * blockDim.x + threadIdx.x;
    if (i >= n4) return;
    float4 v = ((const float4*)src)[i];
    uint32_t* D = (uint32_t*)dst;
    D[2 * i]     = pack_f16(v.x, v.y);
    D[2 * i + 1] = pack_f16(v.z, v.w);
}

// ---------------------------------------------------------------------------
// fp16 HMMA QKV GEMM: C = A @ W^T + bias.  (R13 tiling, 3-stage pipeline)
// CTA 128x128, BK=64, 8 warps (2m x 4n), warp tile 64x32, 2 CTAs/SM.
// smem: XOR-swizzled 128B rows (no pad), 3 stages x 32KB = 96KB.
// ---------------------------------------------------------------------------
#define BM 128
#define BN 128
#define BK 64
#define NCHUNK (GK / BK)                 // 12
#define TILE_B (128 * 128)               // 16384 B (64 fp16 = 128B rows)
#define STAGE_B (2 * TILE_B)             // A | B = 32768 B
#define GEMM_SMEM (3 * STAGE_B)          // 98304 B

// swizzled smem byte address for (row, elem16) where elem16 = 16B-chunk index
__device__ __forceinline__ uint32_t swz(uint32_t row, uint32_t elem16) {
    return row * 128 + ((elem16 ^ (row & 7)) << 4);
}

__device__ __forceinline__ void load_chunk(uint32_t st,
                                           const __half* A, const __half* B,
                                           int bm, int bn, int k0, int tid)
{
#pragma unroll
    for (int t = 0; t < 4; ++t) {        // 1024 x 16B per tile
        int id  = tid + t * 256;
        int r   = id >> 3;               // 0..127
        int seg = id & 7;                // 16B chunk
        uint32_t soff = swz((uint32_t)r, (uint32_t)seg);
        cp_async16(st + soff,          A + (size_t)(bm + r) * GK + k0 + seg * 8);
        cp_async16(st + TILE_B + soff, B + (size_t)(bn + r) * GK + k0 + seg * 8);
    }
}

__global__ __launch_bounds__(256, 2)
void gemm_hmma(const float* __restrict__ bq, const float* __restrict__ bk,
               const float* __restrict__ bv)
{
    extern __shared__ __align__(128) char smem[];
    const int tid  = threadIdx.x;
    const int wid  = tid >> 5;
    const int lane = tid & 31;
    const int sel  = blockIdx.x / 6;
    const int nt6  = blockIdx.x % 6;
    const int bm   = blockIdx.y * BM;
    const int bn   = nt6 * BN;
    const int wm   = wid >> 2;           // 0-1
    const int wn   = wid & 3;            // 0-3

    const __half* __restrict__ A = g_Xh;
    const __half* __restrict__ B = g_Wh[sel];
    __half* __restrict__ C = (sel == 0) ? g_Qh : (sel == 1) ? g_Kh : g_Vh;
    const float* __restrict__ bias = (sel == 0) ? bq : (sel == 1) ? bk : bv;
    // Q pre-scale: 0.125 * log2(e) folded into Q so softmax can use ex2.
    const float outscale = (sel == 0) ? 0.125f * 1.4426950408889634f : 1.0f;

    const uint32_t sb = smem_u32(smem);

    float acc[4][4][4];
#pragma unroll
    for (int i = 0; i < 4; i++)
#pragma unroll
        for (int j = 0; j < 4; j++)
#pragma unroll
            for (int u = 0; u < 4; u++) acc[i][j][u] = 0.f;

    load_chunk(sb, A, B, bm, bn, 0, tid);
    CP_COMMIT();
    load_chunk(sb + STAGE_B, A, B, bm, bn, BK, tid);
    CP_COMMIT();
    load_chunk(sb + 2 * STAGE_B, A, B, bm, bn, 2 * BK, tid);
    CP_COMMIT();

    const uint32_t a_row  = (uint32_t)(wm * 64 + (lane & 15));
    const uint32_t a_ke   = (uint32_t)(lane >> 4);            // elem16 part from lane
    const uint32_t b_row  = (uint32_t)(wn * 32 + (lane & 7) + (((lane >> 4) & 1) << 3));
    const uint32_t b_ke   = (uint32_t)((lane >> 3) & 1);

    int stage = 0;
    for (int c = 0; c < NCHUNK; ++c) {
        CP_WAIT2();                       // >=1 oldest group (chunk c) resident
        __syncthreads();
        const uint32_t st = sb + (uint32_t)stage * STAGE_B;

#pragma unroll
        for (int ks = 0; ks < 4; ++ks) {
            uint32_t af[4][4], bf[2][4];
#pragma unroll
            for (int mt = 0; mt < 4; ++mt)
                ldsm_x4(af[mt], st + swz(a_row + mt * 16, ks * 2 + a_ke));
#pragma unroll
            for (int ng = 0; ng < 2; ++ng)
                ldsm_x4(bf[ng], st + TILE_B + swz(b_row + ng * 16, ks * 2 + b_ke));
#pragma unroll
            for (int mt = 0; mt < 4; ++mt)
#pragma unroll
                for (int ng = 0; ng < 2; ++ng) {
                    mma16816(acc[mt][2 * ng],     af[mt], bf[ng]);
                    mma16816(acc[mt][2 * ng + 1], af[mt], bf[ng] + 2);
                }
        }

        __syncthreads();
        if (c + 3 < NCHUNK)
            load_chunk(sb + (uint32_t)stage * STAGE_B, A, B, bm, bn, (c + 3) * BK, tid);
        CP_COMMIT();                      // uniform group accounting
        stage = (stage == 2) ? 0 : stage + 1;
    }

    // Epilogue: bias add, optional Q pre-scale, fp16 store
#pragma unroll
    for (int nt = 0; nt < 4; ++nt) {
        const int col = bn + wn * 32 + nt * 8 + (lane & 3) * 2;
        const float2 bb = *(const float2*)(bias + col);
#pragma unroll
        for (int mt = 0; mt < 4; ++mt) {
            const int row = bm + wm * 64 + mt * 16 + (lane >> 2);
            size_t i0 = (size_t)row * GN + col;
            size_t i1 = (size_t)(row + 8) * GN + col;
            *(uint32_t*)(C + i0) = pack_f16((acc[mt][nt][0] + bb.x) * outscale,
                                            (acc[mt][nt][1] + bb.y) * outscale);
            *(uint32_t*)(C + i1) = pack_f16((acc[mt][nt][2] + bb.x) * outscale,
                                            (acc[mt][nt][3] + bb.y) * outscale);
        }
    }
}

// ---------------------------------------------------------------------------
// HMMA fused causal flash attention (fp16 Q/K/V, exp2-domain softmax).
// Grid (qt=4, h=12, g=256), 128 threads = 4 warps; warp owns 16 q rows.
// smem: Q | 2 stages x (Kh|Vh) = 46 KB -> 4 CTAs/SM.  (R13 layout, padded)
// ---------------------------------------------------------------------------
#define FSTR 72
#define FTILE_B (64 * FSTR * 2)
#define FQ_B FTILE_B
#define FSTAGE_B (2 * FTILE_B)
#define FLASH_SMEM (FQ_B + 2 * FSTAGE_B) // 46080 B

__device__ __forceinline__ void flash_load_tile(uint32_t base, size_t krow0,
                                                int colh, int tid)
{
#pragma unroll
    for (int i = 0; i < 4; ++i) {
        int id  = tid + i * 128;
        int r   = id >> 3;
        int seg = (id & 7) * 16;
        uint32_t soff = (uint32_t)(r * 144 + seg);
        cp_async16(base + soff,           (const char*)(g_Kh + (krow0 + r) * GN + colh) + seg);
        cp_async16(base + FTILE_B + soff, (const char*)(g_Vh + (krow0 + r) * GN + colh) + seg);
    }
}

__global__ __launch_bounds__(128)
void flash_attn_tc(float* __restrict__ O)
{
    extern __shared__ __align__(128) char smem[];
    const int tid  = threadIdx.x;
    const int warp = tid >> 5;
    const int lane = tid & 31;
    const int qt   = blockIdx.x;
    const int h    = blockIdx.y;
    const int g    = blockIdx.z;
    const int colh = h * 64;
    const size_t qrow0 = (size_t)g * 256 + qt * 64;
    const uint32_t sb = smem_u32(smem);

#pragma unroll
    for (int i = 0; i < 4; ++i) {
        int id  = tid + i * 128;
        int r   = id >> 3;
        int seg = (id & 7) * 16;
        uint32_t soff = (uint32_t)(r * 144 + seg);
        cp_async16(sb + soff, (const char*)(g_Qh + (qrow0 + r) * GN + colh) + seg);
    }
    flash_load_tile(sb + FQ_B, (size_t)g * 256, colh, tid);
    CP_COMMIT();
    if (qt > 0) flash_load_tile(sb + FQ_B + FSTAGE_B, (size_t)g * 256 + 64, colh, tid);
    CP_COMMIT();

    const int lm = lane >> 3;
    const int lr = lane & 7;
    const int r0 = warp * 16;
    const uint32_t a_off0  = (uint32_t)(((r0 + (lm & 1) * 8 + lr) * FSTR + (lm >> 1) * 8) * 2);
    const uint32_t kb_off0 = (uint32_t)((((lm >> 1) * 8 + lr) * FSTR + (lm & 1) * 8) * 2);
    const uint32_t vb_off0 = (uint32_t)((((lm & 1) * 8 + lr) * FSTR + (lm >> 1) * 8) * 2);

    uint32_t qh[4][4];
    float m_[2] = {-1e30f, -1e30f};
    float l_[2] = {0.f, 0.f};
    float o[8][4];
#pragma unroll
    for (int j = 0; j < 8; ++j)
#pragma unroll
        for (int c = 0; c < 4; ++c) o[j][c] = 0.f;

    const int ra = warp * 16 + (lane >> 2);
    const int rb = ra + 8;

    for (int kt = 0; kt <= qt; ++kt) {
        CP_WAIT1();
        __syncthreads();
        const uint32_t kb = sb + FQ_B + (uint32_t)(kt & 1) * FSTAGE_B;

        if (kt == 0) {
#pragma unroll
            for (int kc = 0; kc < 4; ++kc)
                ldsm_x4(qh[kc], sb + a_off0 + kc * 32);
        }

        // ---- S2 = Qs . K^T  (already in log2 domain via Q pre-scale) ----
        float s[8][4];
#pragma unroll
        for (int j = 0; j < 8; ++j)
#pragma unroll
            for (int c = 0; c < 4; ++c) s[j][c] = 0.f;

#pragma unroll
        for (int kc = 0; kc < 4; ++kc)
#pragma unroll
            for (int p = 0; p < 4; ++p) {
                uint32_t kh4[4];
                uint32_t off = kb_off0 + (uint32_t)((p * 16 * FSTR + kc * 16) * 2);
                ldsm_x4(kh4, kb + off);
                mma16816(s[2 * p],     qh[kc], kh4);
                mma16816(s[2 * p + 1], qh[kc], kh4 + 2);
            }

        // ---- causal mask ----
        if (kt == qt) {
#pragma unroll
            for (int j = 0; j < 8; ++j) {
                int k0j = j * 8 + (lane & 3) * 2;
                if (k0j     > ra) s[j][0] = -1e30f;
                if (k0j + 1 > ra) s[j][1] = -1e30f;
                if (k0j     > rb) s[j][2] = -1e30f;
                if (k0j + 1 > rb) s[j][3] = -1e30f;
            }
        }

        // ---- online softmax (exp2 domain) ----
        float mA = -1e30f, mB = -1e30f;
#pragma unroll
        for (int j = 0; j < 8; ++j) {
            mA = fmaxf(mA, fmaxf(s[j][0], s[j][1]));
            mB = fmaxf(mB, fmaxf(s[j][2], s[j][3]));
        }
        mA = fmaxf(mA, __shfl_xor_sync(0xffffffffu, mA, 1));
        mA = fmaxf(mA, __shfl_xor_sync(0xffffffffu, mA, 2));
        mB = fmaxf(mB, __shfl_xor_sync(0xffffffffu, mB, 1));
        mB = fmaxf(mB, __shfl_xor_sync(0xffffffffu, mB, 2));

        float mnA = fmaxf(m_[0], mA), mnB = fmaxf(m_[1], mB);
        float corrA = ex2(m_[0] - mnA), corrB = ex2(m_[1] - mnB);
        m_[0] = mnA; m_[1] = mnB;

        float rsA = 0.f, rsB = 0.f;
#pragma unroll
        for (int j = 0; j < 8; ++j) {
            s[j][0] = ex2(s[j][0] - mnA);
            s[j][1] = ex2(s[j][1] - mnA);
            s[j][2] = ex2(s[j][2] - mnB);
            s[j][3] = ex2(s[j][3] - mnB);
            rsA += s[j][0] + s[j][1];
            rsB += s[j][2] + s[j][3];
        }
        rsA += __shfl_xor_sync(0xffffffffu, rsA, 1);
        rsA += __shfl_xor_sync(0xffffffffu, rsA, 2);
        rsB += __shfl_xor_sync(0xffffffffu, rsB, 1);
        rsB += __shfl_xor_sync(0xffffffffu, rsB, 2);
        l_[0] = l_[0] * corrA + rsA;
        l_[1] = l_[1] * corrB + rsB;

#pragma unroll
        for (int j = 0; j < 8; ++j) {
            o[j][0] *= corrA; o[j][1] *= corrA;
            o[j][2] *= corrB; o[j][3] *= corrB;
        }

        // ---- pack P -> fp16 A-frags ----
        uint32_t ph[4][4];
#pragma unroll
        for (int kc = 0; kc < 4; ++kc) {
            int j0 = 2 * kc, j1 = j0 + 1;
            ph[kc][0] = pack_f16(s[j0][0], s[j0][1]);
            ph[kc][1] = pack_f16(s[j0][2], s[j0][3]);
            ph[kc][2] = pack_f16(s[j1][0], s[j1][1]);
            ph[kc][3] = pack_f16(s[j1][2], s[j1][3]);
        }

        // ---- O += P . V ----
#pragma unroll
        for (int kc = 0; kc < 4; ++kc)
#pragma unroll
            for (int p = 0; p < 4; ++p) {
                uint32_t vh4[4];
                uint32_t off = vb_off0 + (uint32_t)((kc * 16 * FSTR + p * 16) * 2);
                ldsm_x4_t(vh4, kb + FTILE_B + off);
                mma16816(o[2 * p],     ph[kc], vh4);
                mma16816(o[2 * p + 1], ph[kc], vh4 + 2);
            }

        __syncthreads();
        if (kt + 2 <= qt)
            flash_load_tile(sb + FQ_B + (uint32_t)(kt & 1) * FSTAGE_B,
                            (size_t)g * 256 + (kt + 2) * 64, colh, tid);
        CP_COMMIT();
    }

    // ---- epilogue ----
    const float invA = 1.0f / l_[0];
    const float invB = 1.0f / l_[1];
#pragma unroll
    for (int j = 0; j < 8; ++j) {
        const int col = colh + j * 8 + (lane & 3) * 2;
        const size_t rA = qrow0 + warp * 16 + (lane >> 2);
        float2 oa, ob;
        oa.x = o[j][0] * invA; oa.y = o[j][1] * invA;
        ob.x = o[j][2] * invB; ob.y = o[j][3] * invB;
        *(float2*)(O + rA * GN + col) = oa;
        *(float2*)(O + (rA + 8) * GN + col) = ob;
    }
}

// ---------------------------------------------------------------------------
extern "C" void kernel_launch(void* const* d_in, const int* in_sizes, int n_in,
                              void* d_out, int out_size)
{
    const float* X  = (const float*)d_in[0];
    const float* Wq = (const float*)d_in[1];
    const float* bq = (const float*)d_in[2];
    const float* Wk = (const float*)d_in[3];
    const float* bk = (const float*)d_in[4];
    const float* Wv = (const float*)d_in[5];
    const float* bv = (const float*)d_in[6];
    float* O = (float*)d_out;

    __half *xh, *wh;
    cudaGetSymbolAddress((void**)&xh, g_Xh);
    cudaGetSymbolAddress((void**)&wh, g_Wh);

    {
        int n4 = (GM * GK) / 4;
        to_f16<<<(n4 + 255) / 256, 256>>>(X, xh, n4);
        int w4 = (GN * GK) / 4;
        to_f16<<<(w4 + 255) / 256, 256>>>(Wq, wh + 0 * (size_t)GN * GK, w4);
        to_f16<<<(w4 + 255) / 256, 256>>>(Wk, wh + 1 * (size_t)GN * GK, w4);
        to_f16<<<(w4 + 255) / 256, 256>>>(Wv, wh + 2 * (size_t)GN * GK, w4);
    }

    cudaFuncSetAttribute(gemm_hmma, cudaFuncAttributeMaxDynamicSharedMemorySize, GEMM_SMEM);
    dim3 ggrid(18, GM / BM);
    gemm_hmma<<<ggrid, 256, GEMM_SMEM>>>(bq, bk, bv);

    cudaFuncSetAttribute(flash_attn_tc, cudaFuncAttributeMaxDynamicSharedMemorySize, FLASH_SMEM);
    dim3 agrid(4, 12, 256);
    flash_attn_tc<<<agrid, 128, FLASH_SMEM>>>(O);
}

// round 16
// speedup vs baseline: 1.2802x; 1.0277x over previous
#include <cuda_runtime.h>
#include <cuda_fp16.h>
#include <cstdint>
#include <math.h>

#define GM 65536
#define GK 768
#define GN 768

// ---------------------------------------------------------------------------
// Device scratch (allocation-free rule: __device__ globals)
// Q is pre-scaled by 0.125*log2(e) so flash softmax runs in exp2 domain.
// ---------------------------------------------------------------------------
__device__ __half g_Qh[(size_t)GM * GN];
__device__ __half g_Kh[(size_t)GM * GN];
__device__ __half g_Vh[(size_t)GM * GN];
__device__ __half g_Xh[(size_t)GM * GK];
__device__ __half g_Wh[3][(size_t)GN * GK];

// ---------------------------------------------------------------------------
// Baseline-ISA helpers (compute_103-safe)
// ---------------------------------------------------------------------------
__device__ __forceinline__ uint32_t smem_u32(const void* p) {
    uint32_t a;
    asm("{ .reg .u64 t; cvta.to.shared.u64 t, %1; cvt.u32.u64 %0, t; }"
        : "=r"(a) : "l"(p));
    return a;
}

__device__ __forceinline__ void cp_async16(uint32_t saddr, const void* gptr) {
    asm volatile("cp.async.cg.shared.global [%0], [%1], 16;"
                 :: "r"(saddr), "l"(gptr) : "memory");
}
#define CP_COMMIT() asm volatile("cp.async.commit_group;" ::: "memory")
#define CP_WAIT1()  asm volatile("cp.async.wait_group 1;" ::: "memory")
#define CP_WAIT2()  asm volatile("cp.async.wait_group 2;" ::: "memory")

__device__ __forceinline__ void ldsm_x4(uint32_t* r, uint32_t addr) {
    asm volatile("ldmatrix.sync.aligned.m8n8.x4.shared.b16 {%0,%1,%2,%3}, [%4];"
                 : "=r"(r[0]), "=r"(r[1]), "=r"(r[2]), "=r"(r[3]) : "r"(addr));
}
__device__ __forceinline__ void ldsm_x4_t(uint32_t* r, uint32_t addr) {
    asm volatile("ldmatrix.sync.aligned.m8n8.x4.trans.shared.b16 {%0,%1,%2,%3}, [%4];"
                 : "=r"(r[0]), "=r"(r[1]), "=r"(r[2]), "=r"(r[3]) : "r"(addr));
}
// fp16 HMMA, fp32 accumulate
__device__ __forceinline__ void mma16816(float* c, const uint32_t* a, const uint32_t* b) {
    asm volatile(
        "mma.sync.aligned.m16n8k16.row.col.f32.f16.f16.f32 "
        "{%0,%1,%2,%3}, {%4,%5,%6,%7}, {%8,%9}, {%0,%1,%2,%3};"
        : "+f"(c[0]), "+f"(c[1]), "+f"(c[2]), "+f"(c[3])
        : "r"(a[0]), "r"(a[1]), "r"(a[2]), "r"(a[3]), "r"(b[0]), "r"(b[1]));
}
__device__ __forceinline__ uint32_t pack_f16(float lo, float hi) {
    __half2 h = __floats2half2_rn(lo, hi);
    return *(uint32_t*)&h;
}
__device__ __forceinline__ float ex2(float x) {
    float y;
    asm("ex2.approx.ftz.f32 %0, %1;" : "=f"(y) : "f"(x));
    return y;
}

// ---------------------------------------------------------------------------
// fp32 -> fp16 convert
// ---------------------------------------------------------------------------
__global__ void to_f16(const float* __restrict__ src, __half* __restrict__ dst, int n4)
{
    int i = blockIdx.x * blockDim.x + threadIdx.x;
    if (i >= n4) return;
    float4 v = ((const float4*)src)[i];
    uint32_t* D = (uint32_t*)dst;
    D[2 * i]     = pack_f16(v.x, v.y);
    D[2 * i + 1] = pack_f16(v.z, v.w);
}

// ---------------------------------------------------------------------------
// fp16 HMMA QKV GEMM: C = A @ W^T + bias.
// CTA 128x128, BK=64, 4 warps (2m x 2n), warp tile 64x64, 2 CTAs/SM.
// Per warp-chunk: 32 LDSM vs 128 HMMA (0.25 ratio), 3-stage swizzled smem.
// ---------------------------------------------------------------------------
#define BM 128
#define BN 128
#define BK 64
#define NCHUNK (GK / BK)                 // 12
#define TILE_B (128 * 128)               // 16384 B (64 fp16 = 128B rows)
#define STAGE_B (2 * TILE_B)             // A | B = 32768 B
#define GEMM_SMEM (3 * STAGE_B)          // 98304 B

// swizzled smem byte address for (row, elem16) where elem16 = 16B-chunk index
__device__ __forceinline__ uint32_t swz(uint32_t row, uint32_t elem16) {
    return row * 128 + ((elem16 ^ (row & 7)) << 4);
}

__device__ __forceinline__ void load_chunk(uint32_t st,
                                           const __half* A, const __half* B,
                                           int bm, int bn, int k0, int tid)
{
#pragma unroll
    for (int t = 0; t < 8; ++t) {        // 1024 x 16B per tile, 128 threads
        int id  = tid + t * 128;
        int r   = id >> 3;               // 0..127
        int seg = id & 7;                // 16B chunk
        uint32_t soff = swz((uint32_t)r, (uint32_t)seg);
        cp_async16(st + soff,          A + (size_t)(bm + r) * GK + k0 + seg * 8);
        cp_async16(st + TILE_B + soff, B + (size_t)(bn + r) * GK + k0 + seg * 8);
    }
}

__global__ __launch_bounds__(128, 2)
void gemm_hmma(const float* __restrict__ bq, const float* __restrict__ bk,
               const float* __restrict__ bv)
{
    extern __shared__ __align__(128) char smem[];
    const int tid  = threadIdx.x;
    const int wid  = tid >> 5;
    const int lane = tid & 31;
    const int sel  = blockIdx.x / 6;
    const int nt6  = blockIdx.x % 6;
    const int bm   = blockIdx.y * BM;
    const int bn   = nt6 * BN;
    const int wm   = wid >> 1;           // 0-1 -> 64 M rows
    const int wn   = wid & 1;            // 0-1 -> 64 N cols

    const __half* __restrict__ A = g_Xh;
    const __half* __restrict__ B = g_Wh[sel];
    __half* __restrict__ C = (sel == 0) ? g_Qh : (sel == 1) ? g_Kh : g_Vh;
    const float* __restrict__ bias = (sel == 0) ? bq : (sel == 1) ? bk : bv;
    // Q pre-scale: 0.125 * log2(e) folded into Q so softmax can use ex2.
    const float outscale = (sel == 0) ? 0.125f * 1.4426950408889634f : 1.0f;

    const uint32_t sb = smem_u32(smem);

    float acc[4][8][4];
#pragma unroll
    for (int i = 0; i < 4; i++)
#pragma unroll
        for (int j = 0; j < 8; j++)
#pragma unroll
            for (int u = 0; u < 4; u++) acc[i][j][u] = 0.f;

    load_chunk(sb, A, B, bm, bn, 0, tid);
    CP_COMMIT();
    load_chunk(sb + STAGE_B, A, B, bm, bn, BK, tid);
    CP_COMMIT();
    load_chunk(sb + 2 * STAGE_B, A, B, bm, bn, 2 * BK, tid);
    CP_COMMIT();

    const uint32_t a_row  = (uint32_t)(wm * 64 + (lane & 15));
    const uint32_t a_ke   = (uint32_t)(lane >> 4);
    const uint32_t b_row  = (uint32_t)(wn * 64 + (lane & 7) + (((lane >> 4) & 1) << 3));
    const uint32_t b_ke   = (uint32_t)((lane >> 3) & 1);

    int stage = 0;
    for (int c = 0; c < NCHUNK; ++c) {
        CP_WAIT2();                       // chunk c resident
        __syncthreads();
        const uint32_t st = sb + (uint32_t)stage * STAGE_B;

#pragma unroll
        for (int ks = 0; ks < 4; ++ks) {
            uint32_t af[4][4], bf[4][4];
#pragma unroll
            for (int mt = 0; mt < 4; ++mt)
                ldsm_x4(af[mt], st + swz(a_row + mt * 16, ks * 2 + a_ke));
#pragma unroll
            for (int gb = 0; gb < 4; ++gb)
                ldsm_x4(bf[gb], st + TILE_B + swz(b_row + gb * 16, ks * 2 + b_ke));
#pragma unroll
            for (int mt = 0; mt < 4; ++mt)
#pragma unroll
                for (int gb = 0; gb < 4; ++gb) {
                    mma16816(acc[mt][2 * gb],     af[mt], bf[gb]);
                    mma16816(acc[mt][2 * gb + 1], af[mt], bf[gb] + 2);
                }
        }

        __syncthreads();
        if (c + 3 < NCHUNK)
            load_chunk(sb + (uint32_t)stage * STAGE_B, A, B, bm, bn, (c + 3) * BK, tid);
        CP_COMMIT();                      // uniform group accounting
        stage = (stage == 2) ? 0 : stage + 1;
    }

    // Epilogue: bias add, optional Q pre-scale, fp16 store
#pragma unroll
    for (int nt = 0; nt < 8; ++nt) {
        const int col = bn + wn * 64 + nt * 8 + (lane & 3) * 2;
        const float2 bb = *(const float2*)(bias + col);
#pragma unroll
        for (int mt = 0; mt < 4; ++mt) {
            const int row = bm + wm * 64 + mt * 16 + (lane >> 2);
            size_t i0 = (size_t)row * GN + col;
            size_t i1 = (size_t)(row + 8) * GN + col;
            *(uint32_t*)(C + i0) = pack_f16((acc[mt][nt][0] + bb.x) * outscale,
                                            (acc[mt][nt][1] + bb.y) * outscale);
            *(uint32_t*)(C + i1) = pack_f16((acc[mt][nt][2] + bb.x) * outscale,
                                            (acc[mt][nt][3] + bb.y) * outscale);
        }
    }
}

// ---------------------------------------------------------------------------
// HMMA fused causal flash attention (fp16 Q/K/V, exp2-domain softmax).
// Grid (qt=4, h=12, g=256), 128 threads = 4 warps; warp owns 16 q rows.
// smem: Q | 2 stages x (Kh|Vh) = 46 KB -> 4 CTAs/SM.  (unchanged from R15)
// ---------------------------------------------------------------------------
#define FSTR 72
#define FTILE_B (64 * FSTR * 2)
#define FQ_B FTILE_B
#define FSTAGE_B (2 * FTILE_B)
#define FLASH_SMEM (FQ_B + 2 * FSTAGE_B) // 46080 B

__device__ __forceinline__ void flash_load_tile(uint32_t base, size_t krow0,
                                                int colh, int tid)
{
#pragma unroll
    for (int i = 0; i < 4; ++i) {
        int id  = tid + i * 128;
        int r   = id >> 3;
        int seg = (id & 7) * 16;
        uint32_t soff = (uint32_t)(r * 144 + seg);
        cp_async16(base + soff,           (const char*)(g_Kh + (krow0 + r) * GN + colh) + seg);
        cp_async16(base + FTILE_B + soff, (const char*)(g_Vh + (krow0 + r) * GN + colh) + seg);
    }
}

__global__ __launch_bounds__(128)
void flash_attn_tc(float* __restrict__ O)
{
    extern __shared__ __align__(128) char smem[];
    const int tid  = threadIdx.x;
    const int warp = tid >> 5;
    const int lane = tid & 31;
    const int qt   = blockIdx.x;
    const int h    = blockIdx.y;
    const int g    = blockIdx.z;
    const int colh = h * 64;
    const size_t qrow0 = (size_t)g * 256 + qt * 64;
    const uint32_t sb = smem_u32(smem);

#pragma unroll
    for (int i = 0; i < 4; ++i) {
        int id  = tid + i * 128;
        int r   = id >> 3;
        int seg = (id & 7) * 16;
        uint32_t soff = (uint32_t)(r * 144 + seg);
        cp_async16(sb + soff, (const char*)(g_Qh + (qrow0 + r) * GN + colh) + seg);
    }
    flash_load_tile(sb + FQ_B, (size_t)g * 256, colh, tid);
    CP_COMMIT();
    if (qt > 0) flash_load_tile(sb + FQ_B + FSTAGE_B, (size_t)g * 256 + 64, colh, tid);
    CP_COMMIT();

    const int lm = lane >> 3;
    const int lr = lane & 7;
    const int r0 = warp * 16;
    const uint32_t a_off0  = (uint32_t)(((r0 + (lm & 1) * 8 + lr) * FSTR + (lm >> 1) * 8) * 2);
    const uint32_t kb_off0 = (uint32_t)((((lm >> 1) * 8 + lr) * FSTR + (lm & 1) * 8) * 2);
    const uint32_t vb_off0 = (uint32_t)((((lm & 1) * 8 + lr) * FSTR + (lm >> 1) * 8) * 2);

    uint32_t qh[4][4];
    float m_[2] = {-1e30f, -1e30f};
    float l_[2] = {0.f, 0.f};
    float o[8][4];
#pragma unroll
    for (int j = 0; j < 8; ++j)
#pragma unroll
        for (int c = 0; c < 4; ++c) o[j][c] = 0.f;

    const int ra = warp * 16 + (lane >> 2);
    const int rb = ra + 8;

    for (int kt = 0; kt <= qt; ++kt) {
        CP_WAIT1();
        __syncthreads();
        const uint32_t kb = sb + FQ_B + (uint32_t)(kt & 1) * FSTAGE_B;

        if (kt == 0) {
#pragma unroll
            for (int kc = 0; kc < 4; ++kc)
                ldsm_x4(qh[kc], sb + a_off0 + kc * 32);
        }

        float s[8][4];
#pragma unroll
        for (int j = 0; j < 8; ++j)
#pragma unroll
            for (int c = 0; c < 4; ++c) s[j][c] = 0.f;

#pragma unroll
        for (int kc = 0; kc < 4; ++kc)
#pragma unroll
            for (int p = 0; p < 4; ++p) {
                uint32_t kh4[4];
                uint32_t off = kb_off0 + (uint32_t)((p * 16 * FSTR + kc * 16) * 2);
                ldsm_x4(kh4, kb + off);
                mma16816(s[2 * p],     qh[kc], kh4);
                mma16816(s[2 * p + 1], qh[kc], kh4 + 2);
            }

        if (kt == qt) {
#pragma unroll
            for (int j = 0; j < 8; ++j) {
                int k0j = j * 8 + (lane & 3) * 2;
                if (k0j     > ra) s[j][0] = -1e30f;
                if (k0j + 1 > ra) s[j][1] = -1e30f;
                if (k0j     > rb) s[j][2] = -1e30f;
                if (k0j + 1 > rb) s[j][3] = -1e30f;
            }
        }

        float mA = -1e30f, mB = -1e30f;
#pragma unroll
        for (int j = 0; j < 8; ++j) {
            mA = fmaxf(mA, fmaxf(s[j][0], s[j][1]));
            mB = fmaxf(mB, fmaxf(s[j][2], s[j][3]));
        }
        mA = fmaxf(mA, __shfl_xor_sync(0xffffffffu, mA, 1));
        mA = fmaxf(mA, __shfl_xor_sync(0xffffffffu, mA, 2));
        mB = fmaxf(mB, __shfl_xor_sync(0xffffffffu, mB, 1));
        mB = fmaxf(mB, __shfl_xor_sync(0xffffffffu, mB, 2));

        float mnA = fmaxf(m_[0], mA), mnB = fmaxf(m_[1], mB);
        float corrA = ex2(m_[0] - mnA), corrB = ex2(m_[1] - mnB);
        m_[0] = mnA; m_[1] = mnB;

        float rsA = 0.f, rsB = 0.f;
#pragma unroll
        for (int j = 0; j < 8; ++j) {
            s[j][0] = ex2(s[j][0] - mnA);
            s[j][1] = ex2(s[j][1] - mnA);
            s[j][2] = ex2(s[j][2] - mnB);
            s[j][3] = ex2(s[j][3] - mnB);
            rsA += s[j][0] + s[j][1];
            rsB += s[j][2] + s[j][3];
        }
        rsA += __shfl_xor_sync(0xffffffffu, rsA, 1);
        rsA += __shfl_xor_sync(0xffffffffu, rsA, 2);
        rsB += __shfl_xor_sync(0xffffffffu, rsB, 1);
        rsB += __shfl_xor_sync(0xffffffffu, rsB, 2);
        l_[0] = l_[0] * corrA + rsA;
        l_[1] = l_[1] * corrB + rsB;

#pragma unroll
        for (int j = 0; j < 8; ++j) {
            o[j][0] *= corrA; o[j][1] *= corrA;
            o[j][2] *= corrB; o[j][3] *= corrB;
        }

        uint32_t ph[4][4];
#pragma unroll
        for (int kc = 0; kc < 4; ++kc) {
            int j0 = 2 * kc, j1 = j0 + 1;
            ph[kc][0] = pack_f16(s[j0][0], s[j0][1]);
            ph[kc][1] = pack_f16(s[j0][2], s[j0][3]);
            ph[kc][2] = pack_f16(s[j1][0], s[j1][1]);
            ph[kc][3] = pack_f16(s[j1][2], s[j1][3]);
        }

#pragma unroll
        for (int kc = 0; kc < 4; ++kc)
#pragma unroll
            for (int p = 0; p < 4; ++p) {
                uint32_t vh4[4];
                uint32_t off = vb_off0 + (uint32_t)((kc * 16 * FSTR + p * 16) * 2);
                ldsm_x4_t(vh4, kb + FTILE_B + off);
                mma16816(o[2 * p],     ph[kc], vh4);
                mma16816(o[2 * p + 1], ph[kc], vh4 + 2);
            }

        __syncthreads();
        if (kt + 2 <= qt)
            flash_load_tile(sb + FQ_B + (uint32_t)(kt & 1) * FSTAGE_B,
                            (size_t)g * 256 + (kt + 2) * 64, colh, tid);
        CP_COMMIT();
    }

    const float invA = 1.0f / l_[0];
    const float invB = 1.0f / l_[1];
#pragma unroll
    for (int j = 0; j < 8; ++j) {
        const int col = colh + j * 8 + (lane & 3) * 2;
        const size_t rA = qrow0 + warp * 16 + (lane >> 2);
        float2 oa, ob;
        oa.x = o[j][0] * invA; oa.y = o[j][1] * invA;
        ob.x = o[j][2] * invB; ob.y = o[j][3] * invB;
        *(float2*)(O + rA * GN + col) = oa;
        *(float2*)(O + (rA + 8) * GN + col) = ob;
    }
}

// ---------------------------------------------------------------------------
extern "C" void kernel_launch(void* const* d_in, const int* in_sizes, int n_in,
                              void* d_out, int out_size)
{
    const float* X  = (const float*)d_in[0];
    const float* Wq = (const float*)d_in[1];
    const float* bq = (const float*)d_in[2];
    const float* Wk = (const float*)d_in[3];
    const float* bk = (const float*)d_in[4];
    const float* Wv = (const float*)d_in[5];
    const float* bv = (const float*)d_in[6];
    float* O = (float*)d_out;

    __half *xh, *wh;
    cudaGetSymbolAddress((void**)&xh, g_Xh);
    cudaGetSymbolAddress((void**)&wh, g_Wh);

    {
        int n4 = (GM * GK) / 4;
        to_f16<<<(n4 + 255) / 256, 256>>>(X, xh, n4);
        int w4 = (GN * GK) / 4;
        to_f16<<<(w4 + 255) / 256, 256>>>(Wq, wh + 0 * (size_t)GN * GK, w4);
        to_f16<<<(w4 + 255) / 256, 256>>>(Wk, wh + 1 * (size_t)GN * GK, w4);
        to_f16<<<(w4 + 255) / 256, 256>>>(Wv, wh + 2 * (size_t)GN * GK, w4);
    }

    cudaFuncSetAttribute(gemm_hmma, cudaFuncAttributeMaxDynamicSharedMemorySize, GEMM_SMEM);
    dim3 ggrid(18, GM / BM);
    gemm_hmma<<<ggrid, 128, GEMM_SMEM>>>(bq, bk, bv);

    cudaFuncSetAttribute(flash_attn_tc, cudaFuncAttributeMaxDynamicSharedMemorySize, FLASH_SMEM);
    dim3 agrid(4, 12, 256);
    flash_attn_tc<<<agrid, 128, FLASH_SMEM>>>(O);
}